// round 6
// baseline (speedup 1.0000x reference)
#include <cuda_runtime.h>
#include <math.h>

#define SEQ_N 4096
#define BATCH 4
#define CH    1024
#define HEADS 16
#define HD    64
#define M_TOTAL (BATCH * SEQ_N)      // 16384
#define QKV_COLS (3 * CH)            // 3072

// Scratch (device globals: allocation-free per harness rules)
__device__ float g_qkv[(size_t)M_TOTAL * QKV_COLS];   // 192 MB: [qf | kf*valid | v*valid]
__device__ float g_y[(size_t)M_TOTAL * CH];           // 64 MB
__device__ float g_kv[BATCH * HEADS * HD * HD];       // 1 MB
__device__ float g_z[BATCH * HEADS * HD];

// ---------------------------------------------------------------------------
// tf32 tensor-core GEMM, 2-stage double-buffered.
// C[M,N] = A[M,K] @ W[N,K]^T + bias[N] (+ qkv epilogue)
// 128x128x32 CTA tile, 256 threads, warp grid 2(M)x4(N), warp tile 64x32.
// Smem k-pair permutation: pos = (k&3)*2 + ((k>>2)&1) within each k8 group,
// so fragment pairs (k=t, k=t+4) are adjacent -> one LDS.64 each.
// mode==1: columns [0,C) -> phi; [C,2C) -> phi*valid; [2C,3C) -> *valid.
// ---------------------------------------------------------------------------
#define ASTRIDE 40                      // 32 used + 8 pad words
#define STAGE_W (128 * ASTRIDE)         // words per stage per array
#define GEMM_SMEM_BYTES (4 * STAGE_W * 4)   // 2 arrays x 2 stages = 81920 B

__device__ __forceinline__ unsigned f2tf32(float f) {
    unsigned r;
    asm("cvt.rna.tf32.f32 %0, %1;" : "=r"(r) : "f"(f));
    return r;
}

__global__ void __launch_bounds__(256) gemm_tf32_kernel(
    const float* __restrict__ A, const float* __restrict__ W,
    const float* __restrict__ bias, float* __restrict__ C,
    int M, int N, int K, int mode, const int* __restrict__ mask)
{
    extern __shared__ __align__(16) unsigned sh[];
    unsigned* As = sh;                   // [2][STAGE_W]
    unsigned* Bs = sh + 2 * STAGE_W;     // [2][STAGE_W]

    const int tid  = threadIdx.x;
    const int lane = tid & 31;
    const int wid  = tid >> 5;
    const int warp_m = wid & 1;
    const int warp_n = wid >> 1;
    const int g = lane >> 2;
    const int t = lane & 3;

    const int m0 = blockIdx.y * 128;
    const int n0 = blockIdx.x * 128;

    const float* Ab = A + (size_t)m0 * K;
    const float* Wb = W + (size_t)n0 * K;

    // per-thread staging coords: f = tid + r*256 -> row 0..127, kb 0..28
    float acc[4][4][4];
#pragma unroll
    for (int mt = 0; mt < 4; mt++)
#pragma unroll
        for (int nt = 0; nt < 4; nt++)
#pragma unroll
            for (int c = 0; c < 4; c++) acc[mt][nt][c] = 0.f;

    float4 sa[4], sb[4];

    // ---- prologue: load k0=0 tile and fill stage 0 ----
#pragma unroll
    for (int r = 0; r < 4; r++) {
        int f = tid + r * 256, row = f >> 3, kb = (f & 7) << 2;
        sa[r] = *(const float4*)(Ab + (size_t)row * K + kb);
        sb[r] = *(const float4*)(Wb + (size_t)row * K + kb);
    }
#pragma unroll
    for (int r = 0; r < 4; r++) {
        int f = tid + r * 256, row = f >> 3, kb = (f & 7) << 2;
        int grp = (kb >> 3) * 8, hi = (kb >> 2) & 1;
        unsigned* pa = &As[row * ASTRIDE + grp + hi];
        pa[0] = f2tf32(sa[r].x); pa[2] = f2tf32(sa[r].y);
        pa[4] = f2tf32(sa[r].z); pa[6] = f2tf32(sa[r].w);
        unsigned* pb = &Bs[row * ASTRIDE + grp + hi];
        pb[0] = f2tf32(sb[r].x); pb[2] = f2tf32(sb[r].y);
        pb[4] = f2tf32(sb[r].z); pb[6] = f2tf32(sb[r].w);
    }
    __syncthreads();

    int buf = 0;
    for (int k0 = 0; k0 < K; k0 += 32) {
        const bool next = (k0 + 32) < K;

        // ---- issue next-tile gmem loads early (latency hidden by MMAs) ----
        if (next) {
#pragma unroll
            for (int r = 0; r < 4; r++) {
                int f = tid + r * 256, row = f >> 3, kb = (f & 7) << 2;
                sa[r] = *(const float4*)(Ab + (size_t)row * K + k0 + 32 + kb);
                sb[r] = *(const float4*)(Wb + (size_t)row * K + k0 + 32 + kb);
            }
        }

        // ---- compute on current stage ----
        const unsigned* Abs = As + buf * STAGE_W;
        const unsigned* Bbs = Bs + buf * STAGE_W;
#pragma unroll
        for (int kt = 0; kt < 4; kt++) {
            unsigned a[4][4], b[4][2];
#pragma unroll
            for (int mt = 0; mt < 4; mt++) {
                int row = warp_m * 64 + mt * 16 + g;
                uint2 lo = *(const uint2*)&Abs[row * ASTRIDE + kt * 8 + 2 * t];
                uint2 hi = *(const uint2*)&Abs[(row + 8) * ASTRIDE + kt * 8 + 2 * t];
                a[mt][0] = lo.x; a[mt][1] = hi.x; a[mt][2] = lo.y; a[mt][3] = hi.y;
            }
#pragma unroll
            for (int nt = 0; nt < 4; nt++) {
                int rn = warp_n * 32 + nt * 8 + g;
                uint2 bb = *(const uint2*)&Bbs[rn * ASTRIDE + kt * 8 + 2 * t];
                b[nt][0] = bb.x; b[nt][1] = bb.y;
            }
#pragma unroll
            for (int mt = 0; mt < 4; mt++)
#pragma unroll
                for (int nt = 0; nt < 4; nt++) {
                    asm volatile(
                        "mma.sync.aligned.m16n8k8.row.col.f32.tf32.tf32.f32 "
                        "{%0,%1,%2,%3}, {%4,%5,%6,%7}, {%8,%9}, {%0,%1,%2,%3};"
                        : "+f"(acc[mt][nt][0]), "+f"(acc[mt][nt][1]),
                          "+f"(acc[mt][nt][2]), "+f"(acc[mt][nt][3])
                        : "r"(a[mt][0]), "r"(a[mt][1]), "r"(a[mt][2]), "r"(a[mt][3]),
                          "r"(b[nt][0]), "r"(b[nt][1]));
                }
        }

        // ---- store staged regs into the other buffer ----
        if (next) {
            unsigned* Aw = As + (buf ^ 1) * STAGE_W;
            unsigned* Bw = Bs + (buf ^ 1) * STAGE_W;
#pragma unroll
            for (int r = 0; r < 4; r++) {
                int f = tid + r * 256, row = f >> 3, kb = (f & 7) << 2;
                int grp = (kb >> 3) * 8, hi = (kb >> 2) & 1;
                unsigned* pa = &Aw[row * ASTRIDE + grp + hi];
                pa[0] = f2tf32(sa[r].x); pa[2] = f2tf32(sa[r].y);
                pa[4] = f2tf32(sa[r].z); pa[6] = f2tf32(sa[r].w);
                unsigned* pb = &Bw[row * ASTRIDE + grp + hi];
                pb[0] = f2tf32(sb[r].x); pb[2] = f2tf32(sb[r].y);
                pb[4] = f2tf32(sb[r].z); pb[6] = f2tf32(sb[r].w);
            }
        }
        __syncthreads();
        buf ^= 1;
    }

    // ---- epilogue: bias + (phi / mask) + store ----
#pragma unroll
    for (int mt = 0; mt < 4; mt++) {
        const int mr0 = m0 + warp_m * 64 + mt * 16 + g;   // rows mr0, mr0+8
        float valid0 = 1.0f, valid1 = 1.0f;
        if (mode == 1) {
            valid0 = (mask[mr0] != 0) ? 0.0f : 1.0f;
            valid1 = (mask[mr0 + 8] != 0) ? 0.0f : 1.0f;
        }
#pragma unroll
        for (int nt = 0; nt < 4; nt++) {
            const int nc = n0 + warp_n * 32 + nt * 8 + 2 * t;
            float bx = bias[nc], by = bias[nc + 1];
            float v0 = acc[mt][nt][0] + bx;
            float v1 = acc[mt][nt][1] + by;
            float v2 = acc[mt][nt][2] + bx;
            float v3 = acc[mt][nt][3] + by;
            if (mode == 1) {
                if (nc < 2 * CH) {            // q or k -> phi = elu+1
                    v0 = (v0 > 0.f) ? (v0 + 1.0f) : __expf(v0);
                    v1 = (v1 > 0.f) ? (v1 + 1.0f) : __expf(v1);
                    v2 = (v2 > 0.f) ? (v2 + 1.0f) : __expf(v2);
                    v3 = (v3 > 0.f) ? (v3 + 1.0f) : __expf(v3);
                    if (nc >= CH) {           // kf masked
                        v0 *= valid0; v1 *= valid0;
                        v2 *= valid1; v3 *= valid1;
                    }
                } else {                      // v masked
                    v0 *= valid0; v1 *= valid0;
                    v2 *= valid1; v3 *= valid1;
                }
            }
            *(float2*)(C + (size_t)mr0 * N + nc)       = make_float2(v0, v1);
            *(float2*)(C + (size_t)(mr0 + 8) * N + nc) = make_float2(v2, v3);
        }
    }
}

// ---------------------------------------------------------------------------
// Zero kv/z scratch
// ---------------------------------------------------------------------------
__global__ void zero_kernel() {
    int i = blockIdx.x * 256 + threadIdx.x;
    if (i < BATCH * HEADS * HD * HD) g_kv[i] = 0.f;
    if (i < BATCH * HEADS * HD) g_z[i] = 0.f;
}

// ---------------------------------------------------------------------------
// kv[b,h,d,e] = sum_n kf[b,h,n,d] * v[b,h,n,e];  z[b,h,d] = sum_n kf. (fp32)
// ---------------------------------------------------------------------------
__global__ void __launch_bounds__(256) kv_kernel() {
    const int bh = blockIdx.x;
    const int b = bh >> 4, h = bh & 15;
    const int n0 = blockIdx.y * 512;
    const int tid = threadIdx.x;
    const int tx = tid & 15, ty = tid >> 4;

    __shared__ float kf_s[32][64];
    __shared__ float v_s[32][64];

    float acc[4][4];
    float zacc[4];
#pragma unroll
    for (int i = 0; i < 4; i++) {
        zacc[i] = 0.f;
#pragma unroll
        for (int j = 0; j < 4; j++) acc[i][j] = 0.f;
    }

    const float* base = g_qkv + (size_t)(b * SEQ_N + n0) * QKV_COLS + h * HD;

    for (int nt = 0; nt < 512; nt += 32) {
#pragma unroll
        for (int r = 0; r < 8; r++) {
            int e = tid + r * 256;
            int row = e >> 6, col = e & 63;
            size_t gidx = (size_t)(nt + row) * QKV_COLS + col;
            kf_s[row][col] = base[gidx + CH];       // kf (masked)
            v_s[row][col]  = base[gidx + 2 * CH];   // v  (masked)
        }
        __syncthreads();

#pragma unroll 8
        for (int kk = 0; kk < 32; kk++) {
            float a[4], bb[4];
            *(float4*)a  = *(const float4*)&kf_s[kk][ty * 4];
            *(float4*)bb = *(const float4*)&v_s[kk][tx * 4];
#pragma unroll
            for (int i = 0; i < 4; i++) {
                zacc[i] += a[i];
#pragma unroll
                for (int j = 0; j < 4; j++)
                    acc[i][j] = fmaf(a[i], bb[j], acc[i][j]);
            }
        }
        __syncthreads();
    }

    float* kvb = g_kv + (size_t)bh * (HD * HD);
#pragma unroll
    for (int i = 0; i < 4; i++)
#pragma unroll
        for (int j = 0; j < 4; j++)
            atomicAdd(&kvb[(ty * 4 + i) * HD + tx * 4 + j], acc[i][j]);
    if (tx == 0) {
#pragma unroll
        for (int i = 0; i < 4; i++)
            atomicAdd(&g_z[bh * HD + ty * 4 + i], zacc[i]);
    }
}

// ---------------------------------------------------------------------------
// y[b,n,h*64+e] = (qf[b,h,n,:] @ kv[b,h,:,e]) / max(qf·z, EPS)
// Block: 128 n-rows x 64 e. Thread: 4 n x 8 e micro-tile (acc[4][8]).
// q staged in 16-wide d-chunks to stay under static smem limit.
// ---------------------------------------------------------------------------
__global__ void __launch_bounds__(256) y_kernel() {
    const int bh = blockIdx.x;
    const int b = bh >> 4, h = bh & 15;
    const int n0 = blockIdx.y * 128;
    const int tid = threadIdx.x;

    __shared__ float kvs[64][64];       // 16 KB
    __shared__ float zs[64];
    __shared__ float qs[128][20];       // 10 KB (16 used + 4 pad)

    const float* kvb = g_kv + (size_t)bh * (HD * HD);
#pragma unroll
    for (int r = 0; r < 16; r++) {
        int e = tid + r * 256;
        kvs[e >> 6][e & 63] = kvb[e];
    }
    if (tid < 64) zs[tid] = g_z[bh * HD + tid];

    const int eg = (tid & 7) * 8;       // 0..56
    const int nq = tid >> 3;            // 0..31 -> rows nq*4 .. nq*4+3

    float acc[4][8];
    float den[4];
#pragma unroll
    for (int i = 0; i < 4; i++) {
        den[i] = 0.f;
#pragma unroll
        for (int j = 0; j < 8; j++) acc[i][j] = 0.f;
    }

    const float* qbase = g_qkv + (size_t)(b * SEQ_N + n0) * QKV_COLS + h * HD;

    for (int d0 = 0; d0 < 64; d0 += 16) {
        __syncthreads();                 // also covers initial kvs/zs fill
#pragma unroll
        for (int r = 0; r < 2; r++) {
            int e = tid + r * 256;       // 0..511
            int row = e >> 2;            // 0..127
            int c4 = (e & 3) * 4;        // 0,4,8,12
            float4 v = *(const float4*)(qbase + (size_t)row * QKV_COLS + d0 + c4);
            qs[row][c4 + 0] = v.x; qs[row][c4 + 1] = v.y;
            qs[row][c4 + 2] = v.z; qs[row][c4 + 3] = v.w;
        }
        __syncthreads();

#pragma unroll
        for (int dd = 0; dd < 16; dd++) {
            const int d = d0 + dd;
            float bb[8];
            *(float4*)&bb[0] = *(const float4*)&kvs[d][eg];
            *(float4*)&bb[4] = *(const float4*)&kvs[d][eg + 4];
            const float zv = zs[d];
#pragma unroll
            for (int i = 0; i < 4; i++) {
                const float q = qs[nq * 4 + i][dd];
                den[i] = fmaf(q, zv, den[i]);
#pragma unroll
                for (int j = 0; j < 8; j++)
                    acc[i][j] = fmaf(q, bb[j], acc[i][j]);
            }
        }
    }

#pragma unroll
    for (int i = 0; i < 4; i++) {
        const float inv = 1.0f / fmaxf(den[i], 1e-6f);
        float* yp = g_y + (size_t)(b * SEQ_N + n0 + nq * 4 + i) * CH + h * HD + eg;
        *(float4*)yp = make_float4(acc[i][0] * inv, acc[i][1] * inv,
                                   acc[i][2] * inv, acc[i][3] * inv);
        *(float4*)(yp + 4) = make_float4(acc[i][4] * inv, acc[i][5] * inv,
                                         acc[i][6] * inv, acc[i][7] * inv);
    }
}

// ---------------------------------------------------------------------------
extern "C" void kernel_launch(void* const* d_in, const int* in_sizes, int n_in,
                              void* d_out, int out_size)
{
    const float* x     = (const float*)d_in[0];   // [B,N,C]
    const float* W_qkv = (const float*)d_in[1];   // [3C,C]
    const float* b_qkv = (const float*)d_in[2];   // [3C]
    const float* W_out = (const float*)d_in[3];   // [C,C]
    const float* b_out = (const float*)d_in[4];   // [C]
    const int*   mask  = (const int*)d_in[5];     // [B,N] bool->int32, nonzero=PAD

    float* qkv_p; float* y_p;
    cudaGetSymbolAddress((void**)&qkv_p, g_qkv);
    cudaGetSymbolAddress((void**)&y_p, g_y);

    cudaFuncSetAttribute(gemm_tf32_kernel,
                         cudaFuncAttributeMaxDynamicSharedMemorySize,
                         GEMM_SMEM_BYTES);

    // 1) QKV projection + bias + phi + mask epilogue (tf32, double-buffered)
    {
        dim3 grid(QKV_COLS / 128, M_TOTAL / 128);
        gemm_tf32_kernel<<<grid, 256, GEMM_SMEM_BYTES>>>(
            x, W_qkv, b_qkv, qkv_p, M_TOTAL, QKV_COLS, CH, 1, mask);
    }

    // 2) zero kv/z scratch
    zero_kernel<<<(BATCH * HEADS * HD * HD + 255) / 256, 256>>>();

    // 3) kv state + z (fp32)
    {
        dim3 grid(BATCH * HEADS, SEQ_N / 512);
        kv_kernel<<<grid, 256>>>();
    }

    // 4) y = (qf @ kv) / den (fp32, 4x8 micro-tile)
    {
        dim3 grid(BATCH * HEADS, SEQ_N / 128);
        y_kernel<<<grid, 256>>>();
    }

    // 5) output projection (tf32, double-buffered)
    {
        dim3 grid(CH / 128, M_TOTAL / 128);
        gemm_tf32_kernel<<<grid, 256, GEMM_SMEM_BYTES>>>(
            y_p, W_out, b_out, (float*)d_out, M_TOTAL, CH, CH, 0, nullptr);
    }
}

// round 7
// speedup vs baseline: 1.6994x; 1.6994x over previous
#include <cuda_runtime.h>
#include <math.h>

#define SEQ_N 4096
#define BATCH 4
#define CH    1024
#define HEADS 16
#define HD    64
#define M_TOTAL (BATCH * SEQ_N)      // 16384
#define QKV_COLS (3 * CH)            // 3072

// Scratch (device globals: allocation-free per harness rules)
__device__ float g_qkv[(size_t)M_TOTAL * QKV_COLS];   // 192 MB: [qf | kf*valid | v*valid]
__device__ float g_y[(size_t)M_TOTAL * CH];           // 64 MB (tf32 bits, permuted)
__device__ float g_xc[(size_t)M_TOTAL * CH];          // 64 MB x converted+permuted
__device__ float g_wqc[QKV_COLS * CH];                // 12 MB
__device__ float g_woc[CH * CH];                      // 4 MB
__device__ float g_kv[BATCH * HEADS * HD * HD];       // 1 MB
__device__ float g_z[BATCH * HEADS * HD];

__device__ __forceinline__ unsigned f2tf32(float f) {
    unsigned r;
    asm("cvt.rna.tf32.f32 %0, %1;" : "=r"(r) : "f"(f));
    return r;
}

// ---------------------------------------------------------------------------
// convert_permute: fp32 [R,1024] -> tf32-bits, k-pair permuted within each
// 32-column group: pos(k) = (k>>3)*8 + (k&3)*2 + ((k>>2)&1).
// One float4 (4 consecutive k) per thread -> 4 scalar writes grp+hi+{0,2,4,6}.
// ---------------------------------------------------------------------------
__global__ void __launch_bounds__(256) convert_permute(
    const float* __restrict__ in, float* __restrict__ out, int total4)
{
    int idx = blockIdx.x * 256 + threadIdx.x;
    if (idx >= total4) return;
    int idx4 = idx << 2;
    int row = idx4 >> 10;
    int k   = idx4 & 1023;
    int q   = (k >> 2) & 7;
    float4 v = *(const float4*)(in + ((size_t)row << 10) + k);
    unsigned* o = (unsigned*)out + ((size_t)row << 10) + (k & ~31) + (q >> 1) * 8 + (q & 1);
    o[0] = f2tf32(v.x); o[2] = f2tf32(v.y);
    o[4] = f2tf32(v.z); o[6] = f2tf32(v.w);
}

// ---------------------------------------------------------------------------
// tf32 tensor-core GEMM, 2-stage cp.async pipeline.
// A,W are PRE-CONVERTED tf32 bits in the permuted layout; no cvt in mainloop,
// no register staging (LDGSTS gmem->smem direct).
// C[M,N] = A[M,K] @ W[N,K]^T + bias[N] (+ qkv epilogue)
// 128x128x32 CTA tile, 256 threads, warp grid 2(M)x4(N), warp tile 64x32.
// mode==1: columns [0,C) -> phi; [C,2C) -> phi*valid; [2C,3C) -> *valid.
// ---------------------------------------------------------------------------
#define ASTRIDE 40                      // 32 used + 8 pad words
#define STAGE_W (128 * ASTRIDE)
#define GEMM_SMEM_BYTES (4 * STAGE_W * 4)   // A+B, 2 stages = 81920 B

__device__ __forceinline__ void cpasync16(unsigned smem_addr, const void* gptr) {
    asm volatile("cp.async.cg.shared.global [%0], [%1], 16;"
                 :: "r"(smem_addr), "l"(gptr));
}

__global__ void __launch_bounds__(256, 2) gemm_tf32_kernel(
    const float* __restrict__ A, const float* __restrict__ W,
    const float* __restrict__ bias, float* __restrict__ C,
    int M, int N, int K, int mode, const int* __restrict__ mask)
{
    extern __shared__ __align__(16) unsigned sh[];
    unsigned* As = sh;                   // [2][STAGE_W]
    unsigned* Bs = sh + 2 * STAGE_W;

    const int tid  = threadIdx.x;
    const int lane = tid & 31;
    const int wid  = tid >> 5;
    const int warp_m = wid & 1;
    const int warp_n = wid >> 1;
    const int g = lane >> 2;
    const int t = lane & 3;

    const int m0 = blockIdx.y * 128;
    const int n0 = blockIdx.x * 128;

    const float* Ab = A + (size_t)m0 * K;
    const float* Wb = W + (size_t)n0 * K;

    // cp.async coords: f = tid + r*256 (r<4) -> row = f>>3, chunk = f&7 (16B)
    unsigned sA[4], sB[4];
    const unsigned smem_base = (unsigned)__cvta_generic_to_shared(sh);
#pragma unroll
    for (int r = 0; r < 4; r++) {
        int f = tid + r * 256, row = f >> 3, ck = (f & 7) << 2;
        sA[r] = smem_base + (row * ASTRIDE + ck) * 4;
        sB[r] = smem_base + (2 * STAGE_W + row * ASTRIDE + ck) * 4;
    }

    float acc[4][4][4];
#pragma unroll
    for (int mt = 0; mt < 4; mt++)
#pragma unroll
        for (int nt = 0; nt < 4; nt++)
#pragma unroll
            for (int c = 0; c < 4; c++) acc[mt][nt][c] = 0.f;

    // ---- prologue: issue k-tile 0 into stage 0 ----
#pragma unroll
    for (int r = 0; r < 4; r++) {
        int f = tid + r * 256, row = f >> 3, ck = (f & 7) << 2;
        cpasync16(sA[r], Ab + (size_t)row * K + ck);
        cpasync16(sB[r], Wb + (size_t)row * K + ck);
    }
    asm volatile("cp.async.commit_group;");

    int buf = 0;
    for (int k0 = 0; k0 < K; k0 += 32) {
        const bool next = (k0 + 32) < K;
        if (next) {
            const unsigned off = (buf ^ 1) * STAGE_W * 4;
#pragma unroll
            for (int r = 0; r < 4; r++) {
                int f = tid + r * 256, row = f >> 3, ck = (f & 7) << 2;
                cpasync16(sA[r] + off, Ab + (size_t)row * K + k0 + 32 + ck);
                cpasync16(sB[r] + off, Wb + (size_t)row * K + k0 + 32 + ck);
            }
            asm volatile("cp.async.commit_group;");
            asm volatile("cp.async.wait_group 1;");
        } else {
            asm volatile("cp.async.wait_group 0;");
        }
        __syncthreads();

        const unsigned* Abs = As + buf * STAGE_W;
        const unsigned* Bbs = Bs + buf * STAGE_W;
#pragma unroll
        for (int kt = 0; kt < 4; kt++) {
            unsigned a[4][4], b[4][2];
#pragma unroll
            for (int mt = 0; mt < 4; mt++) {
                int row = warp_m * 64 + mt * 16 + g;
                uint2 lo = *(const uint2*)&Abs[row * ASTRIDE + kt * 8 + 2 * t];
                uint2 hi = *(const uint2*)&Abs[(row + 8) * ASTRIDE + kt * 8 + 2 * t];
                a[mt][0] = lo.x; a[mt][1] = hi.x; a[mt][2] = lo.y; a[mt][3] = hi.y;
            }
#pragma unroll
            for (int nt = 0; nt < 4; nt++) {
                int rn = warp_n * 32 + nt * 8 + g;
                uint2 bb = *(const uint2*)&Bbs[rn * ASTRIDE + kt * 8 + 2 * t];
                b[nt][0] = bb.x; b[nt][1] = bb.y;
            }
#pragma unroll
            for (int mt = 0; mt < 4; mt++)
#pragma unroll
                for (int nt = 0; nt < 4; nt++) {
                    asm volatile(
                        "mma.sync.aligned.m16n8k8.row.col.f32.tf32.tf32.f32 "
                        "{%0,%1,%2,%3}, {%4,%5,%6,%7}, {%8,%9}, {%0,%1,%2,%3};"
                        : "+f"(acc[mt][nt][0]), "+f"(acc[mt][nt][1]),
                          "+f"(acc[mt][nt][2]), "+f"(acc[mt][nt][3])
                        : "r"(a[mt][0]), "r"(a[mt][1]), "r"(a[mt][2]), "r"(a[mt][3]),
                          "r"(b[nt][0]), "r"(b[nt][1]));
                }
        }
        __syncthreads();
        buf ^= 1;
    }

    // ---- epilogue: bias + (phi / mask) + store ----
#pragma unroll
    for (int mt = 0; mt < 4; mt++) {
        const int mr0 = m0 + warp_m * 64 + mt * 16 + g;   // rows mr0, mr0+8
        float valid0 = 1.0f, valid1 = 1.0f;
        if (mode == 1) {
            valid0 = (mask[mr0] != 0) ? 0.0f : 1.0f;
            valid1 = (mask[mr0 + 8] != 0) ? 0.0f : 1.0f;
        }
#pragma unroll
        for (int nt = 0; nt < 4; nt++) {
            const int nc = n0 + warp_n * 32 + nt * 8 + 2 * t;
            float bx = bias[nc], by = bias[nc + 1];
            float v0 = acc[mt][nt][0] + bx;
            float v1 = acc[mt][nt][1] + by;
            float v2 = acc[mt][nt][2] + bx;
            float v3 = acc[mt][nt][3] + by;
            if (mode == 1) {
                if (nc < 2 * CH) {            // q or k -> phi = elu+1
                    v0 = (v0 > 0.f) ? (v0 + 1.0f) : __expf(v0);
                    v1 = (v1 > 0.f) ? (v1 + 1.0f) : __expf(v1);
                    v2 = (v2 > 0.f) ? (v2 + 1.0f) : __expf(v2);
                    v3 = (v3 > 0.f) ? (v3 + 1.0f) : __expf(v3);
                    if (nc >= CH) {           // kf masked
                        v0 *= valid0; v1 *= valid0;
                        v2 *= valid1; v3 *= valid1;
                    }
                } else {                      // v masked
                    v0 *= valid0; v1 *= valid0;
                    v2 *= valid1; v3 *= valid1;
                }
            }
            *(float2*)(C + (size_t)mr0 * N + nc)       = make_float2(v0, v1);
            *(float2*)(C + (size_t)(mr0 + 8) * N + nc) = make_float2(v2, v3);
        }
    }
}

// ---------------------------------------------------------------------------
// Zero kv/z scratch
// ---------------------------------------------------------------------------
__global__ void zero_kernel() {
    int i = blockIdx.x * 256 + threadIdx.x;
    if (i < BATCH * HEADS * HD * HD) g_kv[i] = 0.f;
    if (i < BATCH * HEADS * HD) g_z[i] = 0.f;
}

// ---------------------------------------------------------------------------
// kv[b,h,d,e] = sum_n kf[b,h,n,d] * v[b,h,n,e];  z[b,h,d] = sum_n kf. (fp32)
// ---------------------------------------------------------------------------
__global__ void __launch_bounds__(256) kv_kernel() {
    const int bh = blockIdx.x;
    const int b = bh >> 4, h = bh & 15;
    const int n0 = blockIdx.y * 512;
    const int tid = threadIdx.x;
    const int tx = tid & 15, ty = tid >> 4;

    __shared__ float kf_s[32][64];
    __shared__ float v_s[32][64];

    float acc[4][4];
    float zacc[4];
#pragma unroll
    for (int i = 0; i < 4; i++) {
        zacc[i] = 0.f;
#pragma unroll
        for (int j = 0; j < 4; j++) acc[i][j] = 0.f;
    }

    const float* base = g_qkv + (size_t)(b * SEQ_N + n0) * QKV_COLS + h * HD;

    for (int nt = 0; nt < 512; nt += 32) {
#pragma unroll
        for (int r = 0; r < 8; r++) {
            int e = tid + r * 256;
            int row = e >> 6, col = e & 63;
            size_t gidx = (size_t)(nt + row) * QKV_COLS + col;
            kf_s[row][col] = base[gidx + CH];       // kf (masked)
            v_s[row][col]  = base[gidx + 2 * CH];   // v  (masked)
        }
        __syncthreads();

#pragma unroll 8
        for (int kk = 0; kk < 32; kk++) {
            float a[4], bb[4];
            *(float4*)a  = *(const float4*)&kf_s[kk][ty * 4];
            *(float4*)bb = *(const float4*)&v_s[kk][tx * 4];
#pragma unroll
            for (int i = 0; i < 4; i++) {
                zacc[i] += a[i];
#pragma unroll
                for (int j = 0; j < 4; j++)
                    acc[i][j] = fmaf(a[i], bb[j], acc[i][j]);
            }
        }
        __syncthreads();
    }

    float* kvb = g_kv + (size_t)bh * (HD * HD);
#pragma unroll
    for (int i = 0; i < 4; i++)
#pragma unroll
        for (int j = 0; j < 4; j++)
            atomicAdd(&kvb[(ty * 4 + i) * HD + tx * 4 + j], acc[i][j]);
    if (tx == 0) {
#pragma unroll
        for (int i = 0; i < 4; i++)
            atomicAdd(&g_z[bh * HD + ty * 4 + i], zacc[i]);
    }
}

// ---------------------------------------------------------------------------
// y[b,n,h*64+e] = (qf[b,h,n,:] @ kv[b,h,:,e]) / max(qf·z, EPS)
// Block: 128 n-rows x 64 e. Thread: 4n x 8e micro-tile.
// Output written TF32-ROUNDED + K-PAIR PERMUTED (ready for gemm2's cp.async).
// ---------------------------------------------------------------------------
__global__ void __launch_bounds__(256) y_kernel() {
    const int bh = blockIdx.x;
    const int b = bh >> 4, h = bh & 15;
    const int n0 = blockIdx.y * 128;
    const int tid = threadIdx.x;

    __shared__ float kvs[64][64];
    __shared__ float zs[64];
    __shared__ float qs[128][20];

    const float* kvb = g_kv + (size_t)bh * (HD * HD);
#pragma unroll
    for (int r = 0; r < 16; r++) {
        int e = tid + r * 256;
        kvs[e >> 6][e & 63] = kvb[e];
    }
    if (tid < 64) zs[tid] = g_z[bh * HD + tid];

    const int eg = (tid & 7) * 8;
    const int nq = tid >> 3;

    float acc[4][8];
    float den[4];
#pragma unroll
    for (int i = 0; i < 4; i++) {
        den[i] = 0.f;
#pragma unroll
        for (int j = 0; j < 8; j++) acc[i][j] = 0.f;
    }

    const float* qbase = g_qkv + (size_t)(b * SEQ_N + n0) * QKV_COLS + h * HD;

    for (int d0 = 0; d0 < 64; d0 += 16) {
        __syncthreads();
#pragma unroll
        for (int r = 0; r < 2; r++) {
            int e = tid + r * 256;
            int row = e >> 2;
            int c4 = (e & 3) * 4;
            float4 v = *(const float4*)(qbase + (size_t)row * QKV_COLS + d0 + c4);
            qs[row][c4 + 0] = v.x; qs[row][c4 + 1] = v.y;
            qs[row][c4 + 2] = v.z; qs[row][c4 + 3] = v.w;
        }
        __syncthreads();

#pragma unroll
        for (int dd = 0; dd < 16; dd++) {
            const int d = d0 + dd;
            float bb[8];
            *(float4*)&bb[0] = *(const float4*)&kvs[d][eg];
            *(float4*)&bb[4] = *(const float4*)&kvs[d][eg + 4];
            const float zv = zs[d];
#pragma unroll
            for (int i = 0; i < 4; i++) {
                const float q = qs[nq * 4 + i][dd];
                den[i] = fmaf(q, zv, den[i]);
#pragma unroll
                for (int j = 0; j < 8; j++)
                    acc[i][j] = fmaf(q, bb[j], acc[i][j]);
            }
        }
    }

    // store tf32-rounded + permuted: base col h*64+eg is multiple of 8, so the
    // 8 outputs fill one k8 group; pos(j) = (j&3)*2 + ((j>>2)&1).
#pragma unroll
    for (int i = 0; i < 4; i++) {
        const float inv = 1.0f / fmaxf(den[i], 1e-6f);
        unsigned ob[8];
#pragma unroll
        for (int j = 0; j < 8; j++)
            ob[(j & 3) * 2 + ((j >> 2) & 1)] = f2tf32(acc[i][j] * inv);
        unsigned* yp = (unsigned*)g_y
            + (size_t)(b * SEQ_N + n0 + nq * 4 + i) * CH + h * HD + eg;
        *(uint4*)yp       = make_uint4(ob[0], ob[1], ob[2], ob[3]);
        *(uint4*)(yp + 4) = make_uint4(ob[4], ob[5], ob[6], ob[7]);
    }
}

// ---------------------------------------------------------------------------
extern "C" void kernel_launch(void* const* d_in, const int* in_sizes, int n_in,
                              void* d_out, int out_size)
{
    const float* x     = (const float*)d_in[0];   // [B,N,C]
    const float* W_qkv = (const float*)d_in[1];   // [3C,C]
    const float* b_qkv = (const float*)d_in[2];   // [3C]
    const float* W_out = (const float*)d_in[3];   // [C,C]
    const float* b_out = (const float*)d_in[4];   // [C]
    const int*   mask  = (const int*)d_in[5];     // [B,N] bool->int32, nonzero=PAD

    float *qkv_p, *y_p, *xc_p, *wqc_p, *woc_p;
    cudaGetSymbolAddress((void**)&qkv_p, g_qkv);
    cudaGetSymbolAddress((void**)&y_p,   g_y);
    cudaGetSymbolAddress((void**)&xc_p,  g_xc);
    cudaGetSymbolAddress((void**)&wqc_p, g_wqc);
    cudaGetSymbolAddress((void**)&woc_p, g_woc);

    cudaFuncSetAttribute(gemm_tf32_kernel,
                         cudaFuncAttributeMaxDynamicSharedMemorySize,
                         GEMM_SMEM_BYTES);

    // 0) convert + permute operands to tf32
    convert_permute<<<(M_TOTAL * CH / 4 + 255) / 256, 256>>>(x, xc_p, M_TOTAL * CH / 4);
    convert_permute<<<(QKV_COLS * CH / 4 + 255) / 256, 256>>>(W_qkv, wqc_p, QKV_COLS * CH / 4);
    convert_permute<<<(CH * CH / 4 + 255) / 256, 256>>>(W_out, woc_p, CH * CH / 4);

    // 1) QKV projection + bias + phi + mask epilogue (tf32, cp.async pipeline)
    {
        dim3 grid(QKV_COLS / 128, M_TOTAL / 128);
        gemm_tf32_kernel<<<grid, 256, GEMM_SMEM_BYTES>>>(
            xc_p, wqc_p, b_qkv, qkv_p, M_TOTAL, QKV_COLS, CH, 1, mask);
    }

    // 2) zero kv/z scratch
    zero_kernel<<<(BATCH * HEADS * HD * HD + 255) / 256, 256>>>();

    // 3) kv state + z (fp32)
    {
        dim3 grid(BATCH * HEADS, SEQ_N / 512);
        kv_kernel<<<grid, 256>>>();
    }

    // 4) y = (qf @ kv) / den (fp32 compute, tf32-permuted output)
    {
        dim3 grid(BATCH * HEADS, SEQ_N / 128);
        y_kernel<<<grid, 256>>>();
    }

    // 5) output projection (tf32, cp.async pipeline)
    {
        dim3 grid(CH / 128, M_TOTAL / 128);
        gemm_tf32_kernel<<<grid, 256, GEMM_SMEM_BYTES>>>(
            y_p, woc_p, b_out, (float*)d_out, M_TOTAL, CH, CH, 0, nullptr);
    }
}

// round 8
// speedup vs baseline: 1.7027x; 1.0020x over previous
#include <cuda_runtime.h>
#include <math.h>

#define SEQ_N 4096
#define BATCH 4
#define CH    1024
#define HEADS 16
#define HD    64
#define M_TOTAL (BATCH * SEQ_N)      // 16384
#define QKV_COLS (3 * CH)            // 3072

// Scratch (device globals: allocation-free per harness rules)
__device__ float g_qkv[(size_t)M_TOTAL * QKV_COLS];   // 192 MB: [qf | kf*valid | v*valid]
__device__ float g_y[(size_t)M_TOTAL * CH];           // 64 MB (tf32 bits, permuted)
__device__ float g_xc[(size_t)M_TOTAL * CH];          // 64 MB x converted+permuted
__device__ float g_wqc[QKV_COLS * CH];                // 12 MB
__device__ float g_woc[CH * CH];                      // 4 MB
__device__ float g_kv[BATCH * HEADS * HD * HD];       // 1 MB
__device__ float g_z[BATCH * HEADS * HD];

__device__ __forceinline__ unsigned f2tf32(float f) {
    unsigned r;
    asm("cvt.rna.tf32.f32 %0, %1;" : "=r"(r) : "f"(f));
    return r;
}

// ---------------------------------------------------------------------------
// convert_permute: fp32 [R,1024] -> tf32-bits, k-pair permuted within each
// 32-column group: pos(k) = (k>>3)*8 + (k&3)*2 + ((k>>2)&1).
// One float4 (4 consecutive k) per thread -> 4 scalar writes grp+hi+{0,2,4,6}.
// ---------------------------------------------------------------------------
__global__ void __launch_bounds__(256) convert_permute(
    const float* __restrict__ in, float* __restrict__ out, int total4)
{
    int idx = blockIdx.x * 256 + threadIdx.x;
    if (idx >= total4) return;
    int idx4 = idx << 2;
    int row = idx4 >> 10;
    int k   = idx4 & 1023;
    int q   = (k >> 2) & 7;
    float4 v = *(const float4*)(in + ((size_t)row << 10) + k);
    unsigned* o = (unsigned*)out + ((size_t)row << 10) + (k & ~31) + (q >> 1) * 8 + (q & 1);
    o[0] = f2tf32(v.x); o[2] = f2tf32(v.y);
    o[4] = f2tf32(v.z); o[6] = f2tf32(v.w);
}

// ---------------------------------------------------------------------------
// tf32 tensor-core GEMM, 2-stage cp.async pipeline.
// A,W are PRE-CONVERTED tf32 bits in the permuted layout; no cvt in mainloop,
// no register staging (LDGSTS gmem->smem direct).
// C[M,N] = A[M,K] @ W[N,K]^T + bias[N] (+ qkv epilogue)
// 128x128x32 CTA tile, 256 threads, warp grid 2(M)x4(N), warp tile 64x32.
// mode==1: columns [0,C) -> phi; [C,2C) -> phi*valid; [2C,3C) -> *valid.
// ---------------------------------------------------------------------------
#define ASTRIDE 40                      // 32 used + 8 pad words
#define STAGE_W (128 * ASTRIDE)
#define GEMM_SMEM_BYTES (4 * STAGE_W * 4)   // A+B, 2 stages = 81920 B

__device__ __forceinline__ void cpasync16(unsigned smem_addr, const void* gptr) {
    asm volatile("cp.async.cg.shared.global [%0], [%1], 16;"
                 :: "r"(smem_addr), "l"(gptr));
}

__global__ void __launch_bounds__(256, 2) gemm_tf32_kernel(
    const float* __restrict__ A, const float* __restrict__ W,
    const float* __restrict__ bias, float* __restrict__ C,
    int M, int N, int K, int mode, const int* __restrict__ mask)
{
    extern __shared__ __align__(16) unsigned sh[];
    unsigned* As = sh;                   // [2][STAGE_W]
    unsigned* Bs = sh + 2 * STAGE_W;

    const int tid  = threadIdx.x;
    const int lane = tid & 31;
    const int wid  = tid >> 5;
    const int warp_m = wid & 1;
    const int warp_n = wid >> 1;
    const int g = lane >> 2;
    const int t = lane & 3;

    const int m0 = blockIdx.y * 128;
    const int n0 = blockIdx.x * 128;

    const float* Ab = A + (size_t)m0 * K;
    const float* Wb = W + (size_t)n0 * K;

    // cp.async coords: f = tid + r*256 (r<4) -> row = f>>3, chunk = f&7 (16B)
    unsigned sA[4], sB[4];
    const unsigned smem_base = (unsigned)__cvta_generic_to_shared(sh);
#pragma unroll
    for (int r = 0; r < 4; r++) {
        int f = tid + r * 256, row = f >> 3, ck = (f & 7) << 2;
        sA[r] = smem_base + (row * ASTRIDE + ck) * 4;
        sB[r] = smem_base + (2 * STAGE_W + row * ASTRIDE + ck) * 4;
    }

    float acc[4][4][4];
#pragma unroll
    for (int mt = 0; mt < 4; mt++)
#pragma unroll
        for (int nt = 0; nt < 4; nt++)
#pragma unroll
            for (int c = 0; c < 4; c++) acc[mt][nt][c] = 0.f;

    // ---- prologue: issue k-tile 0 into stage 0 ----
#pragma unroll
    for (int r = 0; r < 4; r++) {
        int f = tid + r * 256, row = f >> 3, ck = (f & 7) << 2;
        cpasync16(sA[r], Ab + (size_t)row * K + ck);
        cpasync16(sB[r], Wb + (size_t)row * K + ck);
    }
    asm volatile("cp.async.commit_group;");

    int buf = 0;
    for (int k0 = 0; k0 < K; k0 += 32) {
        const bool next = (k0 + 32) < K;
        if (next) {
            const unsigned off = (buf ^ 1) * STAGE_W * 4;
#pragma unroll
            for (int r = 0; r < 4; r++) {
                int f = tid + r * 256, row = f >> 3, ck = (f & 7) << 2;
                cpasync16(sA[r] + off, Ab + (size_t)row * K + k0 + 32 + ck);
                cpasync16(sB[r] + off, Wb + (size_t)row * K + k0 + 32 + ck);
            }
            asm volatile("cp.async.commit_group;");
            asm volatile("cp.async.wait_group 1;");
        } else {
            asm volatile("cp.async.wait_group 0;");
        }
        __syncthreads();

        const unsigned* Abs = As + buf * STAGE_W;
        const unsigned* Bbs = Bs + buf * STAGE_W;
#pragma unroll
        for (int kt = 0; kt < 4; kt++) {
            unsigned a[4][4], b[4][2];
#pragma unroll
            for (int mt = 0; mt < 4; mt++) {
                int row = warp_m * 64 + mt * 16 + g;
                uint2 lo = *(const uint2*)&Abs[row * ASTRIDE + kt * 8 + 2 * t];
                uint2 hi = *(const uint2*)&Abs[(row + 8) * ASTRIDE + kt * 8 + 2 * t];
                a[mt][0] = lo.x; a[mt][1] = hi.x; a[mt][2] = lo.y; a[mt][3] = hi.y;
            }
#pragma unroll
            for (int nt = 0; nt < 4; nt++) {
                int rn = warp_n * 32 + nt * 8 + g;
                uint2 bb = *(const uint2*)&Bbs[rn * ASTRIDE + kt * 8 + 2 * t];
                b[nt][0] = bb.x; b[nt][1] = bb.y;
            }
#pragma unroll
            for (int mt = 0; mt < 4; mt++)
#pragma unroll
                for (int nt = 0; nt < 4; nt++) {
                    asm volatile(
                        "mma.sync.aligned.m16n8k8.row.col.f32.tf32.tf32.f32 "
                        "{%0,%1,%2,%3}, {%4,%5,%6,%7}, {%8,%9}, {%0,%1,%2,%3};"
                        : "+f"(acc[mt][nt][0]), "+f"(acc[mt][nt][1]),
                          "+f"(acc[mt][nt][2]), "+f"(acc[mt][nt][3])
                        : "r"(a[mt][0]), "r"(a[mt][1]), "r"(a[mt][2]), "r"(a[mt][3]),
                          "r"(b[nt][0]), "r"(b[nt][1]));
                }
        }
        __syncthreads();
        buf ^= 1;
    }

    // ---- epilogue: bias + (phi / mask) + store ----
#pragma unroll
    for (int mt = 0; mt < 4; mt++) {
        const int mr0 = m0 + warp_m * 64 + mt * 16 + g;   // rows mr0, mr0+8
        float valid0 = 1.0f, valid1 = 1.0f;
        if (mode == 1) {
            valid0 = (mask[mr0] != 0) ? 0.0f : 1.0f;
            valid1 = (mask[mr0 + 8] != 0) ? 0.0f : 1.0f;
        }
#pragma unroll
        for (int nt = 0; nt < 4; nt++) {
            const int nc = n0 + warp_n * 32 + nt * 8 + 2 * t;
            float bx = bias[nc], by = bias[nc + 1];
            float v0 = acc[mt][nt][0] + bx;
            float v1 = acc[mt][nt][1] + by;
            float v2 = acc[mt][nt][2] + bx;
            float v3 = acc[mt][nt][3] + by;
            if (mode == 1) {
                if (nc < 2 * CH) {            // q or k -> phi = elu+1
                    v0 = (v0 > 0.f) ? (v0 + 1.0f) : __expf(v0);
                    v1 = (v1 > 0.f) ? (v1 + 1.0f) : __expf(v1);
                    v2 = (v2 > 0.f) ? (v2 + 1.0f) : __expf(v2);
                    v3 = (v3 > 0.f) ? (v3 + 1.0f) : __expf(v3);
                    if (nc >= CH) {           // kf masked
                        v0 *= valid0; v1 *= valid0;
                        v2 *= valid1; v3 *= valid1;
                    }
                } else {                      // v masked
                    v0 *= valid0; v1 *= valid0;
                    v2 *= valid1; v3 *= valid1;
                }
            }
            *(float2*)(C + (size_t)mr0 * N + nc)       = make_float2(v0, v1);
            *(float2*)(C + (size_t)(mr0 + 8) * N + nc) = make_float2(v2, v3);
        }
    }
}

// ---------------------------------------------------------------------------
// Zero kv/z scratch
// ---------------------------------------------------------------------------
__global__ void zero_kernel() {
    int i = blockIdx.x * 256 + threadIdx.x;
    if (i < BATCH * HEADS * HD * HD) g_kv[i] = 0.f;
    if (i < BATCH * HEADS * HD) g_z[i] = 0.f;
}

// ---------------------------------------------------------------------------
// kv[b,h,d,e] = sum_n kf[b,h,n,d] * v[b,h,n,e];  z[b,h,d] = sum_n kf. (fp32)
// ---------------------------------------------------------------------------
__global__ void __launch_bounds__(256) kv_kernel() {
    const int bh = blockIdx.x;
    const int b = bh >> 4, h = bh & 15;
    const int n0 = blockIdx.y * 512;
    const int tid = threadIdx.x;
    const int tx = tid & 15, ty = tid >> 4;

    __shared__ float kf_s[32][64];
    __shared__ float v_s[32][64];

    float acc[4][4];
    float zacc[4];
#pragma unroll
    for (int i = 0; i < 4; i++) {
        zacc[i] = 0.f;
#pragma unroll
        for (int j = 0; j < 4; j++) acc[i][j] = 0.f;
    }

    const float* base = g_qkv + (size_t)(b * SEQ_N + n0) * QKV_COLS + h * HD;

    for (int nt = 0; nt < 512; nt += 32) {
#pragma unroll
        for (int r = 0; r < 8; r++) {
            int e = tid + r * 256;
            int row = e >> 6, col = e & 63;
            size_t gidx = (size_t)(nt + row) * QKV_COLS + col;
            kf_s[row][col] = base[gidx + CH];       // kf (masked)
            v_s[row][col]  = base[gidx + 2 * CH];   // v  (masked)
        }
        __syncthreads();

#pragma unroll 8
        for (int kk = 0; kk < 32; kk++) {
            float a[4], bb[4];
            *(float4*)a  = *(const float4*)&kf_s[kk][ty * 4];
            *(float4*)bb = *(const float4*)&v_s[kk][tx * 4];
#pragma unroll
            for (int i = 0; i < 4; i++) {
                zacc[i] += a[i];
#pragma unroll
                for (int j = 0; j < 4; j++)
                    acc[i][j] = fmaf(a[i], bb[j], acc[i][j]);
            }
        }
        __syncthreads();
    }

    float* kvb = g_kv + (size_t)bh * (HD * HD);
#pragma unroll
    for (int i = 0; i < 4; i++)
#pragma unroll
        for (int j = 0; j < 4; j++)
            atomicAdd(&kvb[(ty * 4 + i) * HD + tx * 4 + j], acc[i][j]);
    if (tx == 0) {
#pragma unroll
        for (int i = 0; i < 4; i++)
            atomicAdd(&g_z[bh * HD + ty * 4 + i], zacc[i]);
    }
}

// ---------------------------------------------------------------------------
// y[b,n,h*64+e] = (qf[b,h,n,:] @ kv[b,h,:,e]) / max(qf·z, EPS)
// Block: 128 n-rows x 64 e. Thread: 4n x 8e micro-tile.
// Output written TF32-ROUNDED + K-PAIR PERMUTED (ready for gemm2's cp.async).
// ---------------------------------------------------------------------------
__global__ void __launch_bounds__(256) y_kernel() {
    const int bh = blockIdx.x;
    const int b = bh >> 4, h = bh & 15;
    const int n0 = blockIdx.y * 128;
    const int tid = threadIdx.x;

    __shared__ float kvs[64][64];
    __shared__ float zs[64];
    __shared__ float qs[128][20];

    const float* kvb = g_kv + (size_t)bh * (HD * HD);
#pragma unroll
    for (int r = 0; r < 16; r++) {
        int e = tid + r * 256;
        kvs[e >> 6][e & 63] = kvb[e];
    }
    if (tid < 64) zs[tid] = g_z[bh * HD + tid];

    const int eg = (tid & 7) * 8;
    const int nq = tid >> 3;

    float acc[4][8];
    float den[4];
#pragma unroll
    for (int i = 0; i < 4; i++) {
        den[i] = 0.f;
#pragma unroll
        for (int j = 0; j < 8; j++) acc[i][j] = 0.f;
    }

    const float* qbase = g_qkv + (size_t)(b * SEQ_N + n0) * QKV_COLS + h * HD;

    for (int d0 = 0; d0 < 64; d0 += 16) {
        __syncthreads();
#pragma unroll
        for (int r = 0; r < 2; r++) {
            int e = tid + r * 256;
            int row = e >> 2;
            int c4 = (e & 3) * 4;
            float4 v = *(const float4*)(qbase + (size_t)row * QKV_COLS + d0 + c4);
            qs[row][c4 + 0] = v.x; qs[row][c4 + 1] = v.y;
            qs[row][c4 + 2] = v.z; qs[row][c4 + 3] = v.w;
        }
        __syncthreads();

#pragma unroll
        for (int dd = 0; dd < 16; dd++) {
            const int d = d0 + dd;
            float bb[8];
            *(float4*)&bb[0] = *(const float4*)&kvs[d][eg];
            *(float4*)&bb[4] = *(const float4*)&kvs[d][eg + 4];
            const float zv = zs[d];
#pragma unroll
            for (int i = 0; i < 4; i++) {
                const float q = qs[nq * 4 + i][dd];
                den[i] = fmaf(q, zv, den[i]);
#pragma unroll
                for (int j = 0; j < 8; j++)
                    acc[i][j] = fmaf(q, bb[j], acc[i][j]);
            }
        }
    }

    // store tf32-rounded + permuted: base col h*64+eg is multiple of 8, so the
    // 8 outputs fill one k8 group; pos(j) = (j&3)*2 + ((j>>2)&1).
#pragma unroll
    for (int i = 0; i < 4; i++) {
        const float inv = 1.0f / fmaxf(den[i], 1e-6f);
        unsigned ob[8];
#pragma unroll
        for (int j = 0; j < 8; j++)
            ob[(j & 3) * 2 + ((j >> 2) & 1)] = f2tf32(acc[i][j] * inv);
        unsigned* yp = (unsigned*)g_y
            + (size_t)(b * SEQ_N + n0 + nq * 4 + i) * CH + h * HD + eg;
        *(uint4*)yp       = make_uint4(ob[0], ob[1], ob[2], ob[3]);
        *(uint4*)(yp + 4) = make_uint4(ob[4], ob[5], ob[6], ob[7]);
    }
}

// ---------------------------------------------------------------------------
extern "C" void kernel_launch(void* const* d_in, const int* in_sizes, int n_in,
                              void* d_out, int out_size)
{
    const float* x     = (const float*)d_in[0];   // [B,N,C]
    const float* W_qkv = (const float*)d_in[1];   // [3C,C]
    const float* b_qkv = (const float*)d_in[2];   // [3C]
    const float* W_out = (const float*)d_in[3];   // [C,C]
    const float* b_out = (const float*)d_in[4];   // [C]
    const int*   mask  = (const int*)d_in[5];     // [B,N] bool->int32, nonzero=PAD

    float *qkv_p, *y_p, *xc_p, *wqc_p, *woc_p;
    cudaGetSymbolAddress((void**)&qkv_p, g_qkv);
    cudaGetSymbolAddress((void**)&y_p,   g_y);
    cudaGetSymbolAddress((void**)&xc_p,  g_xc);
    cudaGetSymbolAddress((void**)&wqc_p, g_wqc);
    cudaGetSymbolAddress((void**)&woc_p, g_woc);

    cudaFuncSetAttribute(gemm_tf32_kernel,
                         cudaFuncAttributeMaxDynamicSharedMemorySize,
                         GEMM_SMEM_BYTES);

    // 0) convert + permute operands to tf32
    convert_permute<<<(M_TOTAL * CH / 4 + 255) / 256, 256>>>(x, xc_p, M_TOTAL * CH / 4);
    convert_permute<<<(QKV_COLS * CH / 4 + 255) / 256, 256>>>(W_qkv, wqc_p, QKV_COLS * CH / 4);
    convert_permute<<<(CH * CH / 4 + 255) / 256, 256>>>(W_out, woc_p, CH * CH / 4);

    // 1) QKV projection + bias + phi + mask epilogue (tf32, cp.async pipeline)
    {
        dim3 grid(QKV_COLS / 128, M_TOTAL / 128);
        gemm_tf32_kernel<<<grid, 256, GEMM_SMEM_BYTES>>>(
            xc_p, wqc_p, b_qkv, qkv_p, M_TOTAL, QKV_COLS, CH, 1, mask);
    }

    // 2) zero kv/z scratch
    zero_kernel<<<(BATCH * HEADS * HD * HD + 255) / 256, 256>>>();

    // 3) kv state + z (fp32)
    {
        dim3 grid(BATCH * HEADS, SEQ_N / 512);
        kv_kernel<<<grid, 256>>>();
    }

    // 4) y = (qf @ kv) / den (fp32 compute, tf32-permuted output)
    {
        dim3 grid(BATCH * HEADS, SEQ_N / 128);
        y_kernel<<<grid, 256>>>();
    }

    // 5) output projection (tf32, cp.async pipeline)
    {
        dim3 grid(CH / 128, M_TOTAL / 128);
        gemm_tf32_kernel<<<grid, 256, GEMM_SMEM_BYTES>>>(
            y_p, woc_p, b_out, (float*)d_out, M_TOTAL, CH, CH, 0, nullptr);
    }
}